// round 2
// baseline (speedup 1.0000x reference)
#include <cuda_runtime.h>
#include <cuda_bf16.h>

#define LL 2048
#define DD 1024
#define GDIM 256

// Scratch (device globals: allocation inside kernel_launch is forbidden)
__device__ float g_q [LL*DD];          // Q, pre-scaled by 1/sqrt(64): [L][1024]
__device__ float g_kb[4*LL*GDIM];      // K per group: [G][L][256]
__device__ float g_vb[4*LL*GDIM];      // V per group: [G][L][256]
__device__ float g_s [8u*LL*LL];       // probs for 8 (g,G) pairs per pass (134 MB)
__device__ float g_o [LL*DD];          // attention output [L][1024]
__device__ float g_y [LL*DD];          // pre-LN residual output

// ---------------------------------------------------------------------------
// 128x128x16 fp32 tiled GEMM, 256 threads, 8x8 micro-tile per thread.
// MODE 0: Q = x@Wq^T * SCALE                          -> g_q
// MODE 1: KV = x@Wkv^T, scatter per-group             -> g_kb / g_vb
// MODE 2: S = Q_g @ K_G^T ; PASS p covers g in {2p,2p+1}; slot bz = glocal*4+G
// MODE 3: O_g = sum_G P_{gG} @ V_G ; bz = glocal; 4 segs over G; pure store
// MODE 4: Y = x + O@Wo^T                              -> g_y
// ---------------------------------------------------------------------------
template<int MODE, int PASS = 0>
__global__ __launch_bounds__(256)
void gemm_k(const float* __restrict__ P0, const float* __restrict__ P1)
{
    constexpr int BM = 128, BN = 128, BK = 16;
    __shared__ float As[BK * BM];   // transposed: As[k][m]
    __shared__ float Bs[BK * BN];   // Bs[k][n]
    const int tid = threadIdx.x;
    const int bx = blockIdx.x, by = blockIdx.y, bz = blockIdx.z;
    const int ty = tid >> 4, tx = tid & 15;
    const int lr = tid >> 1;
    const int lc = (tid & 1) * 8;

    float acc[8][8];
    #pragma unroll
    for (int i = 0; i < 8; i++)
        #pragma unroll
        for (int j = 0; j < 8; j++) acc[i][j] = 0.f;

    const int nseg = (MODE == 3) ? 4 : 1;
    for (int seg = 0; seg < nseg; seg++) {
        const float* Ab; const float* Bb; int lda, ldb, Ks;
        if constexpr (MODE == 0 || MODE == 1) {
            Ab = P0; Bb = P1; lda = DD; ldb = DD; Ks = DD;
        } else if constexpr (MODE == 2) {
            const int glocal = bz >> 2, G = bz & 3;
            const int g = PASS * 2 + glocal;
            Ab = g_q + g * GDIM;                  lda = DD;   Ks = GDIM;
            Bb = g_kb + (size_t)G * LL * GDIM;    ldb = GDIM;
        } else if constexpr (MODE == 3) {
            Ab = g_s  + (size_t)(bz * 4 + seg) * LL * LL;  lda = LL;  Ks = LL;
            Bb = g_vb + (size_t)seg * LL * GDIM;           ldb = GDIM;
        } else {
            Ab = g_o; Bb = P1; lda = DD; ldb = DD; Ks = DD;
        }

        for (int k0 = 0; k0 < Ks; k0 += BK) {
            const float* ap = Ab + (size_t)(by * BM + lr) * lda + k0 + lc;
            float4 av0 = *(const float4*)ap;
            float4 av1 = *(const float4*)(ap + 4);
            As[(lc+0)*BM + lr] = av0.x; As[(lc+1)*BM + lr] = av0.y;
            As[(lc+2)*BM + lr] = av0.z; As[(lc+3)*BM + lr] = av0.w;
            As[(lc+4)*BM + lr] = av1.x; As[(lc+5)*BM + lr] = av1.y;
            As[(lc+6)*BM + lr] = av1.z; As[(lc+7)*BM + lr] = av1.w;
            if constexpr (MODE != 3) {
                const float* bp = Bb + (size_t)(bx * BN + lr) * ldb + k0 + lc;
                float4 bv0 = *(const float4*)bp;
                float4 bv1 = *(const float4*)(bp + 4);
                Bs[(lc+0)*BN + lr] = bv0.x; Bs[(lc+1)*BN + lr] = bv0.y;
                Bs[(lc+2)*BN + lr] = bv0.z; Bs[(lc+3)*BN + lr] = bv0.w;
                Bs[(lc+4)*BN + lr] = bv1.x; Bs[(lc+5)*BN + lr] = bv1.y;
                Bs[(lc+6)*BN + lr] = bv1.z; Bs[(lc+7)*BN + lr] = bv1.w;
            } else {
                const int kk = tid >> 4, nc = (tid & 15) * 8;
                const float* bp = Bb + (size_t)(k0 + kk) * ldb + bx * BN + nc;
                *(float4*)&Bs[kk*BN + nc]     = *(const float4*)bp;
                *(float4*)&Bs[kk*BN + nc + 4] = *(const float4*)(bp + 4);
            }
            __syncthreads();
            #pragma unroll
            for (int kk = 0; kk < BK; kk++) {
                float4 a0 = *(const float4*)&As[kk*BM + ty*8];
                float4 a1 = *(const float4*)&As[kk*BM + ty*8 + 4];
                float4 b0 = *(const float4*)&Bs[kk*BN + tx*8];
                float4 b1 = *(const float4*)&Bs[kk*BN + tx*8 + 4];
                float a[8] = {a0.x,a0.y,a0.z,a0.w,a1.x,a1.y,a1.z,a1.w};
                float b[8] = {b0.x,b0.y,b0.z,b0.w,b1.x,b1.y,b1.z,b1.w};
                #pragma unroll
                for (int i = 0; i < 8; i++)
                    #pragma unroll
                    for (int j = 0; j < 8; j++)
                        acc[i][j] = fmaf(a[i], b[j], acc[i][j]);
            }
            __syncthreads();
        }
    }

    #pragma unroll
    for (int i = 0; i < 8; i++) {
        const int m = by * BM + ty * 8 + i;
        #pragma unroll
        for (int j = 0; j < 8; j++) {
            const int n = bx * BN + tx * 8 + j;
            const float v = acc[i][j];
            if constexpr (MODE == 0) {
                g_q[(size_t)m * DD + n] = v * 0.125f;
            } else if constexpr (MODE == 1) {
                const int head = n >> 7, rem = n & 127;
                const int g2 = head >> 2, h = head & 3;
                if (rem < 64)
                    g_kb[((size_t)g2 * LL + m) * GDIM + h * 64 + rem] = v;
                else
                    g_vb[((size_t)g2 * LL + m) * GDIM + h * 64 + (rem - 64)] = v;
            } else if constexpr (MODE == 2) {
                g_s[(size_t)bz * LL * LL + (size_t)m * LL + n] = v;
            } else if constexpr (MODE == 3) {
                const int g = PASS * 2 + bz;
                g_o[(size_t)m * DD + g * GDIM + n] = v;
            } else {
                g_y[(size_t)m * DD + n] = v + P0[(size_t)m * DD + n];
            }
        }
    }
}

// Row softmax over g_s, in place. One CTA per row; grid = 8*LL.
__global__ __launch_bounds__(256)
void softmax_k()
{
    float* S = g_s + (size_t)blockIdx.x * LL;
    const int tid = threadIdx.x;
    __shared__ float sh[8];
    float v[8];
    float m = -1e30f;
    #pragma unroll
    for (int i = 0; i < 8; i++) { v[i] = S[tid + i * 256]; m = fmaxf(m, v[i]); }
    #pragma unroll
    for (int o = 16; o > 0; o >>= 1) m = fmaxf(m, __shfl_xor_sync(0xffffffffu, m, o));
    if ((tid & 31) == 0) sh[tid >> 5] = m;
    __syncthreads();
    float tm = sh[0];
    #pragma unroll
    for (int w = 1; w < 8; w++) tm = fmaxf(tm, sh[w]);
    __syncthreads();
    float s = 0.f;
    #pragma unroll
    for (int i = 0; i < 8; i++) { v[i] = __expf(v[i] - tm); s += v[i]; }
    #pragma unroll
    for (int o = 16; o > 0; o >>= 1) s += __shfl_xor_sync(0xffffffffu, s, o);
    if ((tid & 31) == 0) sh[tid >> 5] = s;
    __syncthreads();
    float tot = 0.f;
    #pragma unroll
    for (int w = 0; w < 8; w++) tot += sh[w];
    const float inv = 1.0f / tot;
    #pragma unroll
    for (int i = 0; i < 8; i++) S[tid + i * 256] = v[i] * inv;
}

// LayerNorm over g_y rows -> out. One CTA per row.
__global__ __launch_bounds__(256)
void ln_k(const float* __restrict__ gamma, const float* __restrict__ beta,
          float* __restrict__ out)
{
    const int row = blockIdx.x;
    const float* y = g_y + (size_t)row * DD;
    const int tid = threadIdx.x;
    __shared__ float sh[8];
    float v[4]; float s = 0.f;
    #pragma unroll
    for (int i = 0; i < 4; i++) { v[i] = y[tid + i * 256]; s += v[i]; }
    #pragma unroll
    for (int o = 16; o > 0; o >>= 1) s += __shfl_xor_sync(0xffffffffu, s, o);
    if ((tid & 31) == 0) sh[tid >> 5] = s;
    __syncthreads();
    float tot = 0.f;
    #pragma unroll
    for (int w = 0; w < 8; w++) tot += sh[w];
    const float mu = tot * (1.0f / 1024.0f);
    __syncthreads();
    float s2 = 0.f;
    #pragma unroll
    for (int i = 0; i < 4; i++) { const float d = v[i] - mu; s2 += d * d; }
    #pragma unroll
    for (int o = 16; o > 0; o >>= 1) s2 += __shfl_xor_sync(0xffffffffu, s2, o);
    if ((tid & 31) == 0) sh[tid >> 5] = s2;
    __syncthreads();
    float tot2 = 0.f;
    #pragma unroll
    for (int w = 0; w < 8; w++) tot2 += sh[w];
    const float r = rsqrtf(tot2 * (1.0f / 1024.0f) + 1e-5f);
    #pragma unroll
    for (int i = 0; i < 4; i++) {
        const int c = tid + i * 256;
        out[(size_t)row * DD + c] = gamma[c] * (v[i] - mu) * r + beta[c];
    }
}

extern "C" void kernel_launch(void* const* d_in, const int* in_sizes, int n_in,
                              void* d_out, int out_size)
{
    const float* x     = (const float*)d_in[0];
    const float* Wq    = (const float*)d_in[1];
    const float* Wkv   = (const float*)d_in[2];
    const float* Wo    = (const float*)d_in[3];
    const float* gamma = (const float*)d_in[4];
    const float* beta  = (const float*)d_in[5];
    float* out = (float*)d_out;
    (void)in_sizes; (void)n_in; (void)out_size;

    dim3 blk(256);
    gemm_k<0><<<dim3( 8, 16    ), blk>>>(x, Wq);     // Q projection (scaled)
    gemm_k<1><<<dim3(16, 16    ), blk>>>(x, Wkv);    // KV projection + scatter

    // PASS 0: full attention for groups g=0,1 (slots = glocal*4 + G)
    gemm_k<2, 0><<<dim3(16, 16, 8), blk>>>(nullptr, nullptr);
    softmax_k<<<8 * LL, blk>>>();
    gemm_k<3, 0><<<dim3( 2, 16, 2), blk>>>(nullptr, nullptr);
    // PASS 1: groups g=2,3
    gemm_k<2, 1><<<dim3(16, 16, 8), blk>>>(nullptr, nullptr);
    softmax_k<<<8 * LL, blk>>>();
    gemm_k<3, 1><<<dim3( 2, 16, 2), blk>>>(nullptr, nullptr);

    gemm_k<4><<<dim3( 8, 16    ), blk>>>(x, Wo);     // Y = x + O@Wo^T
    ln_k<<<LL, blk>>>(gamma, beta, out);             // LayerNorm -> out
}

// round 3
// speedup vs baseline: 2.2714x; 2.2714x over previous
#include <cuda_runtime.h>
#include <cuda_bf16.h>
#include <cstdint>

#define LL 2048
#define DD 1024
#define GDIM 256

// Scratch (device globals: allocation inside kernel_launch is forbidden)
__device__ float g_q [LL*DD];          // Q, pre-scaled by 1/8: [L][1024]
__device__ float g_kb[4*LL*GDIM];      // K per group: [G][L][256]
__device__ float g_vb[4*LL*GDIM];      // V per group: [G][L][256]
__device__ float g_s [8u*LL*LL];       // probs, 8 (g,G) slots per pass (134 MB)
__device__ float g_o [LL*DD];          // attention output [L][1024]
__device__ float g_y [LL*DD];          // pre-LN residual

// ---------------------------------------------------------------------------
// PTX wrappers
// ---------------------------------------------------------------------------
__device__ __forceinline__ void ldsm4(uint32_t* r, const __nv_bfloat16* p) {
    uint32_t a = (uint32_t)__cvta_generic_to_shared(p);
    asm volatile("ldmatrix.sync.aligned.m8n8.x4.shared.b16 {%0,%1,%2,%3}, [%4];"
                 : "=r"(r[0]), "=r"(r[1]), "=r"(r[2]), "=r"(r[3]) : "r"(a));
}
__device__ __forceinline__ void ldsm4t(uint32_t* r, const __nv_bfloat16* p) {
    uint32_t a = (uint32_t)__cvta_generic_to_shared(p);
    asm volatile("ldmatrix.sync.aligned.m8n8.x4.trans.shared.b16 {%0,%1,%2,%3}, [%4];"
                 : "=r"(r[0]), "=r"(r[1]), "=r"(r[2]), "=r"(r[3]) : "r"(a));
}
__device__ __forceinline__ void mma16816(float* c, const uint32_t* a,
                                         uint32_t b0, uint32_t b1) {
    asm volatile("mma.sync.aligned.m16n8k16.row.col.f32.bf16.bf16.f32 "
                 "{%0,%1,%2,%3}, {%4,%5,%6,%7}, {%8,%9}, {%0,%1,%2,%3};"
                 : "+f"(c[0]), "+f"(c[1]), "+f"(c[2]), "+f"(c[3])
                 : "r"(a[0]), "r"(a[1]), "r"(a[2]), "r"(a[3]), "r"(b0), "r"(b1));
}
__device__ __forceinline__ void split_bf16(float v, __nv_bfloat16& h, __nv_bfloat16& l) {
    h = __float2bfloat16_rn(v);
    l = __float2bfloat16_rn(v - __bfloat162float(h));
}

// ---------------------------------------------------------------------------
// Tensor-core GEMM, 128x128x32 tiles, 256 thr = 8 warps (4m x 2n), warp 32x64.
// fp32 operands split into bf16 hi/lo; acc += Ah*Bh + Ah*Bl + Al*Bh.
// MODE 0: Q = x@Wq^T * 0.125 -> g_q   (also zeroes g_o)
// MODE 1: KV = x@Wkv^T, scatter -> g_kb/g_vb
// MODE 2: S = Q_g @ K_G^T; PASS p: g = 2p + (bz>>2), G = bz&3; slot = bz
// MODE 3: O[:, g*256:] += P_slot @ V_G; bz: glocal=bz>>2, G=bz&3 (atomicAdd)
// MODE 4: Y = x + O@Wo^T -> g_y
// ---------------------------------------------------------------------------
template<int MODE, int PASS = 0>
__global__ __launch_bounds__(256, 1)
void gemm_tc(const float* __restrict__ P0, const float* __restrict__ P1)
{
    constexpr int BM = 128, BN = 128, BK = 32;
    constexpr int SA = 40;                         // padded bf16 row stride (A, k-contig B)
    constexpr int SBR = (MODE == 3) ? BK : BN;     // B smem rows
    constexpr int SBS = (MODE == 3) ? 136 : 40;    // B smem stride
    __shared__ __nv_bfloat16 Ah[BM * SA], Al[BM * SA];
    __shared__ __nv_bfloat16 Bh[SBR * SBS], Bl[SBR * SBS];

    const int tid = threadIdx.x, lane = tid & 31, w = tid >> 5;
    const int wm = w & 3, wn = w >> 2;             // warp grid 4x2
    const int bx = blockIdx.x, by = blockIdx.y, bz = blockIdx.z;

    float acc[2][8][4];
    #pragma unroll
    for (int i = 0; i < 2; i++)
        #pragma unroll
        for (int j = 0; j < 8; j++)
            #pragma unroll
            for (int k = 0; k < 4; k++) acc[i][j][k] = 0.f;

    // operand bases
    const float* Ab; const float* Bb; int lda, ldb, Ks;
    if constexpr (MODE == 0 || MODE == 1) {
        Ab = P0; Bb = P1; lda = DD; ldb = DD; Ks = DD;
    } else if constexpr (MODE == 2) {
        const int glocal = bz >> 2, G = bz & 3;
        const int g = PASS * 2 + glocal;
        Ab = g_q + g * GDIM;               lda = DD;   Ks = GDIM;
        Bb = g_kb + (size_t)G * LL * GDIM; ldb = GDIM;
    } else if constexpr (MODE == 3) {
        const int G = bz & 3;
        Ab = g_s + (size_t)bz * LL * LL;   lda = LL;   Ks = LL;
        Bb = g_vb + (size_t)G * LL * GDIM; ldb = GDIM;
    } else {
        Ab = g_o; Bb = P1; lda = DD; ldb = DD; Ks = DD;
    }

    for (int k0 = 0; k0 < Ks; k0 += BK) {
        // ---- stage A: 128 rows, k-contiguous; 2 thr/row x 16 floats ----
        {
            const int sr = tid >> 1, sc = (tid & 1) * 16;
            const float* ap = Ab + (size_t)(by * BM + sr) * lda + k0 + sc;
            float4 v[4];
            v[0] = *(const float4*)(ap + 0);  v[1] = *(const float4*)(ap + 4);
            v[2] = *(const float4*)(ap + 8);  v[3] = *(const float4*)(ap + 12);
            const float* f = (const float*)v;
            __nv_bfloat162* dh = (__nv_bfloat162*)&Ah[sr * SA + sc];
            __nv_bfloat162* dl = (__nv_bfloat162*)&Al[sr * SA + sc];
            #pragma unroll
            for (int j = 0; j < 8; j++) {
                __nv_bfloat16 h0, l0, h1, l1;
                split_bf16(f[2*j],   h0, l0);
                split_bf16(f[2*j+1], h1, l1);
                __nv_bfloat162 ph; ph.x = h0; ph.y = h1;
                __nv_bfloat162 pl; pl.x = l0; pl.y = l1;
                dh[j] = ph; dl[j] = pl;
            }
        }
        // ---- stage B ----
        if constexpr (MODE != 3) {
            const int sr = tid >> 1, sc = (tid & 1) * 16;
            const float* bp = Bb + (size_t)(bx * BN + sr) * ldb + k0 + sc;
            float4 v[4];
            v[0] = *(const float4*)(bp + 0);  v[1] = *(const float4*)(bp + 4);
            v[2] = *(const float4*)(bp + 8);  v[3] = *(const float4*)(bp + 12);
            const float* f = (const float*)v;
            __nv_bfloat162* dh = (__nv_bfloat162*)&Bh[sr * SA + sc];
            __nv_bfloat162* dl = (__nv_bfloat162*)&Bl[sr * SA + sc];
            #pragma unroll
            for (int j = 0; j < 8; j++) {
                __nv_bfloat16 h0, l0, h1, l1;
                split_bf16(f[2*j],   h0, l0);
                split_bf16(f[2*j+1], h1, l1);
                __nv_bfloat162 ph; ph.x = h0; ph.y = h1;
                __nv_bfloat162 pl; pl.x = l0; pl.y = l1;
                dh[j] = ph; dl[j] = pl;
            }
        } else {
            // B tile is [k=32][n contiguous 128]: 8 thr/row x 16 floats
            const int sr = tid >> 3, sc = (tid & 7) * 16;
            const float* bp = Bb + (size_t)(k0 + sr) * ldb + bx * BN + sc;
            float4 v[4];
            v[0] = *(const float4*)(bp + 0);  v[1] = *(const float4*)(bp + 4);
            v[2] = *(const float4*)(bp + 8);  v[3] = *(const float4*)(bp + 12);
            const float* f = (const float*)v;
            __nv_bfloat162* dh = (__nv_bfloat162*)&Bh[sr * SBS + sc];
            __nv_bfloat162* dl = (__nv_bfloat162*)&Bl[sr * SBS + sc];
            #pragma unroll
            for (int j = 0; j < 8; j++) {
                __nv_bfloat16 h0, l0, h1, l1;
                split_bf16(f[2*j],   h0, l0);
                split_bf16(f[2*j+1], h1, l1);
                __nv_bfloat162 ph; ph.x = h0; ph.y = h1;
                __nv_bfloat162 pl; pl.x = l0; pl.y = l1;
                dh[j] = ph; dl[j] = pl;
            }
        }
        __syncthreads();

        // ---- compute: 2 k-steps of 16 ----
        #pragma unroll
        for (int ks = 0; ks < 2; ks++) {
            uint32_t ah[2][4], al[2][4];
            const int ar = wm * 32 + (lane & 15);
            const int ac = ks * 16 + (lane >> 4) * 8;
            #pragma unroll
            for (int mt = 0; mt < 2; mt++) {
                ldsm4(ah[mt], &Ah[(ar + mt * 16) * SA + ac]);
                ldsm4(al[mt], &Al[(ar + mt * 16) * SA + ac]);
            }
            #pragma unroll
            for (int ntp = 0; ntp < 4; ntp++) {
                uint32_t bh[4], bl[4];
                uint32_t b0h, b1h, b0l, b1l, c0h, c1h, c0l, c1l;
                if constexpr (MODE != 3) {
                    const int br = wn * 64 + ntp * 16 + (lane & 15);
                    const int bc = ks * 16 + (lane >> 4) * 8;
                    ldsm4(bh, &Bh[br * SBS + bc]);
                    ldsm4(bl, &Bl[br * SBS + bc]);
                    // regs: 0=b0(nt0) 1=b0(nt1) 2=b1(nt0) 3=b1(nt1)
                    b0h = bh[0]; b1h = bh[2]; c0h = bh[1]; c1h = bh[3];
                    b0l = bl[0]; b1l = bl[2]; c0l = bl[1]; c1l = bl[3];
                } else {
                    const int br = ks * 16 + (lane & 15);            // k
                    const int bc = wn * 64 + ntp * 16 + (lane >> 4) * 8; // n
                    ldsm4t(bh, &Bh[br * SBS + bc]);
                    ldsm4t(bl, &Bl[br * SBS + bc]);
                    // regs: 0,1 = nt0 (b0,b1); 2,3 = nt1
                    b0h = bh[0]; b1h = bh[1]; c0h = bh[2]; c1h = bh[3];
                    b0l = bl[0]; b1l = bl[1]; c0l = bl[2]; c1l = bl[3];
                }
                #pragma unroll
                for (int mt = 0; mt < 2; mt++) {
                    mma16816(acc[mt][2*ntp],   ah[mt], b0h, b1h);
                    mma16816(acc[mt][2*ntp],   ah[mt], b0l, b1l);
                    mma16816(acc[mt][2*ntp],   al[mt], b0h, b1h);
                    mma16816(acc[mt][2*ntp+1], ah[mt], c0h, c1h);
                    mma16816(acc[mt][2*ntp+1], ah[mt], c0l, c1l);
                    mma16816(acc[mt][2*ntp+1], al[mt], c0h, c1h);
                }
            }
        }
        __syncthreads();
    }

    // ---- epilogue: c frag (m16n8): c0=(r,c) c1=(r,c+1) c2=(r+8,c) c3=(r+8,c+1)
    const int er = lane >> 2, ec = 2 * (lane & 3);
    #pragma unroll
    for (int mt = 0; mt < 2; mt++) {
        #pragma unroll
        for (int nt = 0; nt < 8; nt++) {
            #pragma unroll
            for (int q = 0; q < 4; q++) {
                const int m = by * BM + wm * 32 + mt * 16 + er + (q >> 1) * 8;
                const int n = bx * BN + wn * 64 + nt * 8 + ec + (q & 1);
                const float v = acc[mt][nt][q];
                if constexpr (MODE == 0) {
                    g_q[(size_t)m * DD + n] = v * 0.125f;
                    g_o[(size_t)m * DD + n] = 0.f;          // pre-zero for MODE 3
                } else if constexpr (MODE == 1) {
                    const int head = n >> 7, rem = n & 127;
                    const int g2 = head >> 2, h = head & 3;
                    if (rem < 64)
                        g_kb[((size_t)g2 * LL + m) * GDIM + h * 64 + rem] = v;
                    else
                        g_vb[((size_t)g2 * LL + m) * GDIM + h * 64 + (rem - 64)] = v;
                } else if constexpr (MODE == 2) {
                    g_s[(size_t)bz * LL * LL + (size_t)m * LL + n] = v;
                } else if constexpr (MODE == 3) {
                    const int g = PASS * 2 + (bz >> 2);
                    atomicAdd(&g_o[(size_t)m * DD + g * GDIM + n], v);
                } else {
                    g_y[(size_t)m * DD + n] = v + P0[(size_t)m * DD + n];
                }
            }
        }
    }
}

// Row softmax over g_s, in place. One CTA per row; grid = 8*LL.
__global__ __launch_bounds__(256)
void softmax_k()
{
    float* S = g_s + (size_t)blockIdx.x * LL;
    const int tid = threadIdx.x;
    __shared__ float sh[8];
    float v[8];
    float m = -1e30f;
    #pragma unroll
    for (int i = 0; i < 8; i++) { v[i] = S[tid + i * 256]; m = fmaxf(m, v[i]); }
    #pragma unroll
    for (int o = 16; o > 0; o >>= 1) m = fmaxf(m, __shfl_xor_sync(0xffffffffu, m, o));
    if ((tid & 31) == 0) sh[tid >> 5] = m;
    __syncthreads();
    float tm = sh[0];
    #pragma unroll
    for (int w = 1; w < 8; w++) tm = fmaxf(tm, sh[w]);
    __syncthreads();
    float s = 0.f;
    #pragma unroll
    for (int i = 0; i < 8; i++) { v[i] = __expf(v[i] - tm); s += v[i]; }
    #pragma unroll
    for (int o = 16; o > 0; o >>= 1) s += __shfl_xor_sync(0xffffffffu, s, o);
    if ((tid & 31) == 0) sh[tid >> 5] = s;
    __syncthreads();
    float tot = 0.f;
    #pragma unroll
    for (int w = 0; w < 8; w++) tot += sh[w];
    const float inv = 1.0f / tot;
    #pragma unroll
    for (int i = 0; i < 8; i++) S[tid + i * 256] = v[i] * inv;
}

// LayerNorm over g_y rows -> out. One CTA per row.
__global__ __launch_bounds__(256)
void ln_k(const float* __restrict__ gamma, const float* __restrict__ beta,
          float* __restrict__ out)
{
    const int row = blockIdx.x;
    const float* y = g_y + (size_t)row * DD;
    const int tid = threadIdx.x;
    __shared__ float sh[8];
    float v[4]; float s = 0.f;
    #pragma unroll
    for (int i = 0; i < 4; i++) { v[i] = y[tid + i * 256]; s += v[i]; }
    #pragma unroll
    for (int o = 16; o > 0; o >>= 1) s += __shfl_xor_sync(0xffffffffu, s, o);
    if ((tid & 31) == 0) sh[tid >> 5] = s;
    __syncthreads();
    float tot = 0.f;
    #pragma unroll
    for (int w = 0; w < 8; w++) tot += sh[w];
    const float mu = tot * (1.0f / 1024.0f);
    __syncthreads();
    float s2 = 0.f;
    #pragma unroll
    for (int i = 0; i < 4; i++) { const float d = v[i] - mu; s2 += d * d; }
    #pragma unroll
    for (int o = 16; o > 0; o >>= 1) s2 += __shfl_xor_sync(0xffffffffu, s2, o);
    if ((tid & 31) == 0) sh[tid >> 5] = s2;
    __syncthreads();
    float tot2 = 0.f;
    #pragma unroll
    for (int w = 0; w < 8; w++) tot2 += sh[w];
    const float r = rsqrtf(tot2 * (1.0f / 1024.0f) + 1e-5f);
    #pragma unroll
    for (int i = 0; i < 4; i++) {
        const int c = tid + i * 256;
        out[(size_t)row * DD + c] = gamma[c] * (v[i] - mu) * r + beta[c];
    }
}

extern "C" void kernel_launch(void* const* d_in, const int* in_sizes, int n_in,
                              void* d_out, int out_size)
{
    const float* x     = (const float*)d_in[0];
    const float* Wq    = (const float*)d_in[1];
    const float* Wkv   = (const float*)d_in[2];
    const float* Wo    = (const float*)d_in[3];
    const float* gamma = (const float*)d_in[4];
    const float* beta  = (const float*)d_in[5];
    float* out = (float*)d_out;
    (void)in_sizes; (void)n_in; (void)out_size;

    dim3 blk(256);
    gemm_tc<0><<<dim3( 8, 16    ), blk>>>(x, Wq);     // Q proj (scaled) + zero g_o
    gemm_tc<1><<<dim3(16, 16    ), blk>>>(x, Wkv);    // KV proj + scatter

    // PASS 0: groups g=0,1 (slots bz = glocal*4 + G)
    gemm_tc<2, 0><<<dim3(16, 16, 8), blk>>>(nullptr, nullptr);
    softmax_k<<<8 * LL, blk>>>();
    gemm_tc<3, 0><<<dim3( 2, 16, 8), blk>>>(nullptr, nullptr);
    // PASS 1: groups g=2,3
    gemm_tc<2, 1><<<dim3(16, 16, 8), blk>>>(nullptr, nullptr);
    softmax_k<<<8 * LL, blk>>>();
    gemm_tc<3, 1><<<dim3( 2, 16, 8), blk>>>(nullptr, nullptr);

    gemm_tc<4><<<dim3( 8, 16    ), blk>>>(x, Wo);     // Y = x + O@Wo^T
    ln_k<<<LL, blk>>>(gamma, beta, out);              // LayerNorm -> out
}

// round 4
// speedup vs baseline: 6.0382x; 2.6584x over previous
#include <cuda_runtime.h>
#include <cuda_bf16.h>
#include <cstdint>

#define LL 2048
#define DD 1024
#define GDIM 256

typedef __nv_bfloat16 bf16;
typedef __nv_bfloat162 bf162;

// Scratch (device globals; allocation in kernel_launch is forbidden)
__device__ bf16  g_xb [LL*DD];        // x in bf16
__device__ bf16  g_wq [DD*DD];        // Wq bf16
__device__ bf16  g_wkv[2*DD*DD];      // Wkv bf16
__device__ bf16  g_wo [DD*DD];        // Wo bf16
__device__ bf16  g_q  [LL*DD];        // Q bf16, pre-scaled by 1/8
__device__ bf16  g_kb [4*LL*GDIM];    // K per group [G][L][256]
__device__ bf16  g_vb [4*LL*GDIM];    // V per group [G][L][256]
__device__ bf16  g_s  [16u*LL*LL];    // scores/probs bf16, 16 slots (134 MB)
__device__ bf16  g_ob [LL*DD];        // attention output bf16
__device__ float g_y  [LL*DD];        // pre-LN residual fp32

// ---------------------------------------------------------------------------
// PTX wrappers
// ---------------------------------------------------------------------------
__device__ __forceinline__ void ldsm4(uint32_t* r, const bf16* p) {
    uint32_t a = (uint32_t)__cvta_generic_to_shared(p);
    asm volatile("ldmatrix.sync.aligned.m8n8.x4.shared.b16 {%0,%1,%2,%3}, [%4];"
                 : "=r"(r[0]), "=r"(r[1]), "=r"(r[2]), "=r"(r[3]) : "r"(a));
}
__device__ __forceinline__ void ldsm4t(uint32_t* r, const bf16* p) {
    uint32_t a = (uint32_t)__cvta_generic_to_shared(p);
    asm volatile("ldmatrix.sync.aligned.m8n8.x4.trans.shared.b16 {%0,%1,%2,%3}, [%4];"
                 : "=r"(r[0]), "=r"(r[1]), "=r"(r[2]), "=r"(r[3]) : "r"(a));
}
__device__ __forceinline__ void mma16816(float* c, const uint32_t* a,
                                         uint32_t b0, uint32_t b1) {
    asm volatile("mma.sync.aligned.m16n8k16.row.col.f32.bf16.bf16.f32 "
                 "{%0,%1,%2,%3}, {%4,%5,%6,%7}, {%8,%9}, {%0,%1,%2,%3};"
                 : "+f"(c[0]), "+f"(c[1]), "+f"(c[2]), "+f"(c[3])
                 : "r"(a[0]), "r"(a[1]), "r"(a[2]), "r"(a[3]), "r"(b0), "r"(b1));
}
__device__ __forceinline__ bf162 pack2(float a, float b) {
    bf162 r; r.x = __float2bfloat16_rn(a); r.y = __float2bfloat16_rn(b); return r;
}

// ---------------------------------------------------------------------------
// fp32 -> bf16 conversion (one-shot staging of inputs)
// ---------------------------------------------------------------------------
__global__ __launch_bounds__(256)
void cvt_k(const float* __restrict__ in, bf16* __restrict__ out, int n)
{
    const int i = (blockIdx.x * 256 + threadIdx.x) * 4;
    if (i < n) {
        float4 v = *(const float4*)(in + i);
        *(bf162*)(out + i)     = pack2(v.x, v.y);
        *(bf162*)(out + i + 2) = pack2(v.z, v.w);
    }
}

// ---------------------------------------------------------------------------
// Single-pass bf16 tensor-core GEMM. 128x128x32 tiles, 8 warps (4m x 2n),
// warp tile 32x64, mma.sync m16n8k16, fp32 accumulate.
// MODE 0: Q = x@Wq^T * 0.125       -> g_q  (bf16)
// MODE 1: KV = x@Wkv^T, scatter    -> g_kb / g_vb (bf16)
// MODE 2: S = Q_g @ K_G^T ; bz = slot = g*4+G  -> g_s (bf16)
// MODE 3: O_g = sum_G P_{g,G} @ V_G ; bz = g, 4 segs -> g_ob (bf16)
// MODE 4: Y = x + O@Wo^T           -> g_y (fp32; P0 = x fp32 residual)
// ---------------------------------------------------------------------------
template<int MODE>
__global__ __launch_bounds__(256, 2)
void gemm_tc(const float* __restrict__ P0)
{
    constexpr int BM = 128, BN = 128, BK = 32;
    constexpr int SA  = 40;                       // A smem stride (bf16)
    constexpr int SBR = (MODE == 3) ? BK : BN;
    constexpr int SBS = (MODE == 3) ? 136 : 40;
    __shared__ alignas(16) bf16 As[BM * SA];
    __shared__ alignas(16) bf16 Bs[SBR * SBS];

    const int tid = threadIdx.x, lane = tid & 31, w = tid >> 5;
    const int wm = w & 3, wn = w >> 2;
    const int bx = blockIdx.x, by = blockIdx.y, bz = blockIdx.z;

    float acc[2][8][4];
    #pragma unroll
    for (int i = 0; i < 2; i++)
        #pragma unroll
        for (int j = 0; j < 8; j++)
            #pragma unroll
            for (int k = 0; k < 4; k++) acc[i][j][k] = 0.f;

    const int nseg = (MODE == 3) ? 4 : 1;
    for (int seg = 0; seg < nseg; seg++) {
        const bf16* Ab; const bf16* Bb; int lda, ldb, Ks;
        if constexpr (MODE == 0) {
            Ab = g_xb; Bb = g_wq;  lda = DD; ldb = DD; Ks = DD;
        } else if constexpr (MODE == 1) {
            Ab = g_xb; Bb = g_wkv; lda = DD; ldb = DD; Ks = DD;
        } else if constexpr (MODE == 2) {
            const int g = bz >> 2, G = bz & 3;
            Ab = g_q + g * GDIM;               lda = DD;   Ks = GDIM;
            Bb = g_kb + (size_t)G * LL * GDIM; ldb = GDIM;
        } else if constexpr (MODE == 3) {
            Ab = g_s + (size_t)(bz * 4 + seg) * LL * LL;  lda = LL; Ks = LL;
            Bb = g_vb + (size_t)seg * LL * GDIM;          ldb = GDIM;
        } else {
            Ab = g_ob; Bb = g_wo; lda = DD; ldb = DD; Ks = DD;
        }

        for (int k0 = 0; k0 < Ks; k0 += BK) {
            // ---- stage A: 128 rows x 32 bf16, 2 thr/row ----
            {
                const int sr = tid >> 1, sc = (tid & 1) * 16;
                const bf16* ap = Ab + (size_t)(by * BM + sr) * lda + k0 + sc;
                *(uint4*)&As[sr * SA + sc]     = *(const uint4*)ap;
                *(uint4*)&As[sr * SA + sc + 8] = *(const uint4*)(ap + 8);
            }
            // ---- stage B ----
            if constexpr (MODE != 3) {
                const int sr = tid >> 1, sc = (tid & 1) * 16;
                const bf16* bp = Bb + (size_t)(bx * BN + sr) * ldb + k0 + sc;
                *(uint4*)&Bs[sr * SBS + sc]     = *(const uint4*)bp;
                *(uint4*)&Bs[sr * SBS + sc + 8] = *(const uint4*)(bp + 8);
            } else {
                // [k=32][n=128] tile, n-contiguous rows; 8 thr/row
                const int sr = tid >> 3, sc = (tid & 7) * 16;
                const bf16* bp = Bb + (size_t)(k0 + sr) * ldb + bx * BN + sc;
                *(uint4*)&Bs[sr * SBS + sc]     = *(const uint4*)bp;
                *(uint4*)&Bs[sr * SBS + sc + 8] = *(const uint4*)(bp + 8);
            }
            __syncthreads();

            // ---- compute: 2 k-steps of 16 ----
            #pragma unroll
            for (int ks = 0; ks < 2; ks++) {
                uint32_t ah[2][4];
                const int ar = wm * 32 + (lane & 15);
                const int ac = ks * 16 + (lane >> 4) * 8;
                #pragma unroll
                for (int mt = 0; mt < 2; mt++)
                    ldsm4(ah[mt], &As[(ar + mt * 16) * SA + ac]);
                #pragma unroll
                for (int ntp = 0; ntp < 4; ntp++) {
                    uint32_t bh[4];
                    uint32_t b0, b1, c0, c1;
                    if constexpr (MODE != 3) {
                        const int br = wn * 64 + ntp * 16 + (lane & 15);
                        const int bc = ks * 16 + (lane >> 4) * 8;
                        ldsm4(bh, &Bs[br * SBS + bc]);
                        b0 = bh[0]; b1 = bh[2]; c0 = bh[1]; c1 = bh[3];
                    } else {
                        const int br = ks * 16 + (lane & 15);
                        const int bc = wn * 64 + ntp * 16 + (lane >> 4) * 8;
                        ldsm4t(bh, &Bs[br * SBS + bc]);
                        b0 = bh[0]; b1 = bh[1]; c0 = bh[2]; c1 = bh[3];
                    }
                    #pragma unroll
                    for (int mt = 0; mt < 2; mt++) {
                        mma16816(acc[mt][2*ntp],   ah[mt], b0, b1);
                        mma16816(acc[mt][2*ntp+1], ah[mt], c0, c1);
                    }
                }
            }
            __syncthreads();
        }
    }

    // ---- epilogue: frag c0=(r,c) c1=(r,c+1) c2=(r+8,c) c3=(r+8,c+1) ----
    const int er = lane >> 2, ec = 2 * (lane & 3);
    #pragma unroll
    for (int mt = 0; mt < 2; mt++) {
        #pragma unroll
        for (int nt = 0; nt < 8; nt++) {
            #pragma unroll
            for (int q2 = 0; q2 < 2; q2++) {
                const int m  = by * BM + wm * 32 + mt * 16 + er + q2 * 8;
                const int n0 = bx * BN + wn * 64 + nt * 8 + ec;
                const float v0 = acc[mt][nt][2*q2], v1 = acc[mt][nt][2*q2+1];
                if constexpr (MODE == 0) {
                    *(bf162*)&g_q[(size_t)m * DD + n0] = pack2(v0*0.125f, v1*0.125f);
                } else if constexpr (MODE == 1) {
                    const int head = n0 >> 7, rem = n0 & 127;
                    const int g2 = head >> 2, h = head & 3;
                    if (rem < 64)
                        *(bf162*)&g_kb[((size_t)g2*LL + m)*GDIM + h*64 + rem] = pack2(v0, v1);
                    else
                        *(bf162*)&g_vb[((size_t)g2*LL + m)*GDIM + h*64 + rem - 64] = pack2(v0, v1);
                } else if constexpr (MODE == 2) {
                    *(bf162*)&g_s[(size_t)bz*LL*LL + (size_t)m*LL + n0] = pack2(v0, v1);
                } else if constexpr (MODE == 3) {
                    *(bf162*)&g_ob[(size_t)m*DD + bz*GDIM + n0] = pack2(v0, v1);
                } else {
                    g_y[(size_t)m*DD + n0]     = v0 + P0[(size_t)m*DD + n0];
                    g_y[(size_t)m*DD + n0 + 1] = v1 + P0[(size_t)m*DD + n0 + 1];
                }
            }
        }
    }
}

// ---------------------------------------------------------------------------
// Row softmax over bf16 g_s, in place. One CTA per row; grid = 16*LL.
// ---------------------------------------------------------------------------
__global__ __launch_bounds__(256)
void softmax_k()
{
    bf16* S = g_s + (size_t)blockIdx.x * LL;
    const int tid = threadIdx.x;
    __shared__ float sh[8];
    uint4 raw = *(const uint4*)(S + tid * 8);
    const bf162* p2 = (const bf162*)&raw;
    float v[8];
    #pragma unroll
    for (int i = 0; i < 4; i++) {
        float2 f = __bfloat1622float2(p2[i]);
        v[2*i] = f.x; v[2*i+1] = f.y;
    }
    float m = -1e30f;
    #pragma unroll
    for (int i = 0; i < 8; i++) m = fmaxf(m, v[i]);
    #pragma unroll
    for (int o = 16; o > 0; o >>= 1) m = fmaxf(m, __shfl_xor_sync(0xffffffffu, m, o));
    if ((tid & 31) == 0) sh[tid >> 5] = m;
    __syncthreads();
    float tm = sh[0];
    #pragma unroll
    for (int w = 1; w < 8; w++) tm = fmaxf(tm, sh[w]);
    __syncthreads();
    float s = 0.f;
    #pragma unroll
    for (int i = 0; i < 8; i++) { v[i] = __expf(v[i] - tm); s += v[i]; }
    #pragma unroll
    for (int o = 16; o > 0; o >>= 1) s += __shfl_xor_sync(0xffffffffu, s, o);
    if ((tid & 31) == 0) sh[tid >> 5] = s;
    __syncthreads();
    float tot = 0.f;
    #pragma unroll
    for (int w = 0; w < 8; w++) tot += sh[w];
    const float inv = 1.0f / tot;
    uint4 out;
    bf162* o2 = (bf162*)&out;
    #pragma unroll
    for (int i = 0; i < 4; i++) o2[i] = pack2(v[2*i] * inv, v[2*i+1] * inv);
    *(uint4*)(S + tid * 8) = out;
}

// ---------------------------------------------------------------------------
// LayerNorm over g_y rows -> out. One CTA per row.
// ---------------------------------------------------------------------------
__global__ __launch_bounds__(256)
void ln_k(const float* __restrict__ gamma, const float* __restrict__ beta,
          float* __restrict__ out)
{
    const int row = blockIdx.x;
    const float* y = g_y + (size_t)row * DD;
    const int tid = threadIdx.x;
    __shared__ float sh[8];
    float v[4]; float s = 0.f;
    #pragma unroll
    for (int i = 0; i < 4; i++) { v[i] = y[tid + i * 256]; s += v[i]; }
    #pragma unroll
    for (int o = 16; o > 0; o >>= 1) s += __shfl_xor_sync(0xffffffffu, s, o);
    if ((tid & 31) == 0) sh[tid >> 5] = s;
    __syncthreads();
    float tot = 0.f;
    #pragma unroll
    for (int w = 0; w < 8; w++) tot += sh[w];
    const float mu = tot * (1.0f / 1024.0f);
    __syncthreads();
    float s2 = 0.f;
    #pragma unroll
    for (int i = 0; i < 4; i++) { const float d = v[i] - mu; s2 += d * d; }
    #pragma unroll
    for (int o = 16; o > 0; o >>= 1) s2 += __shfl_xor_sync(0xffffffffu, s2, o);
    if ((tid & 31) == 0) sh[tid >> 5] = s2;
    __syncthreads();
    float tot2 = 0.f;
    #pragma unroll
    for (int w = 0; w < 8; w++) tot2 += sh[w];
    const float r = rsqrtf(tot2 * (1.0f / 1024.0f) + 1e-5f);
    #pragma unroll
    for (int i = 0; i < 4; i++) {
        const int c = tid + i * 256;
        out[(size_t)row * DD + c] = gamma[c] * (v[i] - mu) * r + beta[c];
    }
}

extern "C" void kernel_launch(void* const* d_in, const int* in_sizes, int n_in,
                              void* d_out, int out_size)
{
    const float* x     = (const float*)d_in[0];
    const float* Wq    = (const float*)d_in[1];
    const float* Wkv   = (const float*)d_in[2];
    const float* Wo    = (const float*)d_in[3];
    const float* gamma = (const float*)d_in[4];
    const float* beta  = (const float*)d_in[5];
    float* out = (float*)d_out;
    (void)in_sizes; (void)n_in; (void)out_size;

    bf16 *xb, *wq, *wkv, *wo;
    cudaGetSymbolAddress((void**)&xb,  g_xb);
    cudaGetSymbolAddress((void**)&wq,  g_wq);
    cudaGetSymbolAddress((void**)&wkv, g_wkv);
    cudaGetSymbolAddress((void**)&wo,  g_wo);

    dim3 blk(256);
    cvt_k<<<LL*DD/1024,   blk>>>(x,   xb,  LL*DD);
    cvt_k<<<DD*DD/1024,   blk>>>(Wq,  wq,  DD*DD);
    cvt_k<<<2*DD*DD/1024, blk>>>(Wkv, wkv, 2*DD*DD);
    cvt_k<<<DD*DD/1024,   blk>>>(Wo,  wo,  DD*DD);

    gemm_tc<0><<<dim3( 8, 16    ), blk>>>(nullptr);  // Q proj (scaled, bf16)
    gemm_tc<1><<<dim3(16, 16    ), blk>>>(nullptr);  // KV proj + scatter (bf16)
    gemm_tc<2><<<dim3(16, 16, 16), blk>>>(nullptr);  // 16 (g,G) score GEMMs
    softmax_k<<<16 * LL, blk>>>();                   // row softmax, in place
    gemm_tc<3><<<dim3( 2, 16,  4), blk>>>(nullptr);  // O_g = sum_G P@V (bf16)
    gemm_tc<4><<<dim3( 8, 16    ), blk>>>(x);        // Y = x + O@Wo^T (fp32)
    ln_k<<<LL, blk>>>(gamma, beta, out);             // LayerNorm -> out
}

// round 5
// speedup vs baseline: 7.2414x; 1.1993x over previous
#include <cuda_runtime.h>
#include <cuda_bf16.h>
#include <cstdint>

#define LL 2048
#define DD 1024
#define GDIM 256

typedef __nv_bfloat16 bf16;
typedef __nv_bfloat162 bf162;

// Scratch (device globals; allocation in kernel_launch is forbidden)
__device__ bf16  g_xb [LL*DD];
__device__ bf16  g_wq [DD*DD];
__device__ bf16  g_wkv[2*DD*DD];
__device__ bf16  g_wo [DD*DD];
__device__ bf16  g_q  [LL*DD];        // Q bf16, pre-scaled by 1/8
__device__ bf16  g_kb [4*LL*GDIM];    // K per group [G][L][256]
__device__ bf16  g_vb [4*LL*GDIM];    // V per group [G][L][256]
__device__ bf16  g_s  [16u*LL*LL];    // scores/probs bf16, 16 slots (134 MB)
__device__ bf16  g_ob [LL*DD];        // attention output bf16
__device__ float g_y  [LL*DD];        // pre-LN residual fp32

// ---------------------------------------------------------------------------
// PTX wrappers
// ---------------------------------------------------------------------------
__device__ __forceinline__ void ldsm4(uint32_t* r, const bf16* p) {
    uint32_t a = (uint32_t)__cvta_generic_to_shared(p);
    asm volatile("ldmatrix.sync.aligned.m8n8.x4.shared.b16 {%0,%1,%2,%3}, [%4];"
                 : "=r"(r[0]), "=r"(r[1]), "=r"(r[2]), "=r"(r[3]) : "r"(a));
}
__device__ __forceinline__ void ldsm4t(uint32_t* r, const bf16* p) {
    uint32_t a = (uint32_t)__cvta_generic_to_shared(p);
    asm volatile("ldmatrix.sync.aligned.m8n8.x4.trans.shared.b16 {%0,%1,%2,%3}, [%4];"
                 : "=r"(r[0]), "=r"(r[1]), "=r"(r[2]), "=r"(r[3]) : "r"(a));
}
__device__ __forceinline__ void mma16816(float* c, const uint32_t* a,
                                         uint32_t b0, uint32_t b1) {
    asm volatile("mma.sync.aligned.m16n8k16.row.col.f32.bf16.bf16.f32 "
                 "{%0,%1,%2,%3}, {%4,%5,%6,%7}, {%8,%9}, {%0,%1,%2,%3};"
                 : "+f"(c[0]), "+f"(c[1]), "+f"(c[2]), "+f"(c[3])
                 : "r"(a[0]), "r"(a[1]), "r"(a[2]), "r"(a[3]), "r"(b0), "r"(b1));
}
__device__ __forceinline__ void cp16(bf16* dst, const bf16* src) {
    uint32_t d = (uint32_t)__cvta_generic_to_shared(dst);
    asm volatile("cp.async.cg.shared.global [%0], [%1], 16;" :: "r"(d), "l"(src) : "memory");
}
__device__ __forceinline__ void cp_commit() {
    asm volatile("cp.async.commit_group;" ::: "memory");
}
__device__ __forceinline__ void cp_wait0() {
    asm volatile("cp.async.wait_group 0;" ::: "memory");
}
__device__ __forceinline__ bf162 pack2(float a, float b) {
    bf162 r; r.x = __float2bfloat16_rn(a); r.y = __float2bfloat16_rn(b); return r;
}

// ---------------------------------------------------------------------------
__global__ __launch_bounds__(256)
void cvt_k(const float* __restrict__ in, bf16* __restrict__ out, int n)
{
    const int i = (blockIdx.x * 256 + threadIdx.x) * 4;
    if (i < n) {
        float4 v = *(const float4*)(in + i);
        *(bf162*)(out + i)     = pack2(v.x, v.y);
        *(bf162*)(out + i + 2) = pack2(v.z, v.w);
    }
}

// ---------------------------------------------------------------------------
// bf16 tensor-core GEMM, cp.async 2-stage pipeline.
// 128x128x32 tiles, 8 warps (4m x 2n), warp tile 32x64, mma.sync m16n8k16.
// MODE 0: Q = x@Wq^T * 0.125       -> g_q
// MODE 1: KV = x@Wkv^T, scatter    -> g_kb/g_vb
// MODE 2: S = Q_g @ K_G^T ; bz = g*4+G -> g_s
// MODE 3: O_g = sum_G P_{g,G} @ V_G ; bz = g, 4 segs -> g_ob
// MODE 4: Y = x + O@Wo^T           -> g_y
// ---------------------------------------------------------------------------
template<int MODE>
__global__ __launch_bounds__(256, 2)
void gemm_tc(const float* __restrict__ P0)
{
    constexpr int BM = 128, BN = 128, BK = 32;
    constexpr int SA  = 40;
    constexpr int SBR = (MODE == 3) ? BK : BN;
    constexpr int SBS = (MODE == 3) ? 136 : 40;
    __shared__ alignas(16) bf16 As[2][BM * SA];
    __shared__ alignas(16) bf16 Bs[2][SBR * SBS];

    const int tid = threadIdx.x, lane = tid & 31, w = tid >> 5;
    const int wm = w & 3, wn = w >> 2;
    const int bx = blockIdx.x, by = blockIdx.y, bz = blockIdx.z;

    float acc[2][8][4];
    #pragma unroll
    for (int i = 0; i < 2; i++)
        #pragma unroll
        for (int j = 0; j < 8; j++)
            #pragma unroll
            for (int k = 0; k < 4; k++) acc[i][j][k] = 0.f;

    const int nseg = (MODE == 3) ? 4 : 1;
    for (int seg = 0; seg < nseg; seg++) {
        const bf16* Ab; const bf16* Bb; int lda, ldb, Ks;
        if constexpr (MODE == 0) {
            Ab = g_xb; Bb = g_wq;  lda = DD; ldb = DD; Ks = DD;
        } else if constexpr (MODE == 1) {
            Ab = g_xb; Bb = g_wkv; lda = DD; ldb = DD; Ks = DD;
        } else if constexpr (MODE == 2) {
            const int g = bz >> 2, G = bz & 3;
            Ab = g_q + g * GDIM;               lda = DD;   Ks = GDIM;
            Bb = g_kb + (size_t)G * LL * GDIM; ldb = GDIM;
        } else if constexpr (MODE == 3) {
            Ab = g_s + (size_t)(bz * 4 + seg) * LL * LL;  lda = LL; Ks = LL;
            Bb = g_vb + (size_t)seg * LL * GDIM;          ldb = GDIM;
        } else {
            Ab = g_ob; Bb = g_wo; lda = DD; ldb = DD; Ks = DD;
        }

        // stage loader (cp.async)
        auto stage = [&](int buf, int k0) {
            {
                const int sr = tid >> 1, sc = (tid & 1) * 16;
                const bf16* ap = Ab + (size_t)(by * BM + sr) * lda + k0 + sc;
                cp16(&As[buf][sr * SA + sc],     ap);
                cp16(&As[buf][sr * SA + sc + 8], ap + 8);
            }
            if constexpr (MODE != 3) {
                const int sr = tid >> 1, sc = (tid & 1) * 16;
                const bf16* bp = Bb + (size_t)(bx * BN + sr) * ldb + k0 + sc;
                cp16(&Bs[buf][sr * SBS + sc],     bp);
                cp16(&Bs[buf][sr * SBS + sc + 8], bp + 8);
            } else {
                const int sr = tid >> 3, sc = (tid & 7) * 16;
                const bf16* bp = Bb + (size_t)(k0 + sr) * ldb + bx * BN + sc;
                cp16(&Bs[buf][sr * SBS + sc],     bp);
                cp16(&Bs[buf][sr * SBS + sc + 8], bp + 8);
            }
            cp_commit();
        };

        const int nk = Ks / BK;
        stage(0, 0);                               // prologue
        for (int ki = 0; ki < nk; ki++) {
            const int buf = ki & 1;
            cp_wait0();
            __syncthreads();
            if (ki + 1 < nk) stage(buf ^ 1, (ki + 1) * BK);  // overlap next load

            // ---- compute current buffer: 2 k-steps of 16 ----
            #pragma unroll
            for (int ks = 0; ks < 2; ks++) {
                uint32_t ah[2][4];
                const int ar = wm * 32 + (lane & 15);
                const int ac = ks * 16 + (lane >> 4) * 8;
                #pragma unroll
                for (int mt = 0; mt < 2; mt++)
                    ldsm4(ah[mt], &As[buf][(ar + mt * 16) * SA + ac]);
                #pragma unroll
                for (int ntp = 0; ntp < 4; ntp++) {
                    uint32_t bh[4];
                    uint32_t b0, b1, c0, c1;
                    if constexpr (MODE != 3) {
                        const int br = wn * 64 + ntp * 16 + (lane & 15);
                        const int bc = ks * 16 + (lane >> 4) * 8;
                        ldsm4(bh, &Bs[buf][br * SBS + bc]);
                        b0 = bh[0]; b1 = bh[2]; c0 = bh[1]; c1 = bh[3];
                    } else {
                        const int br = ks * 16 + (lane & 15);
                        const int bc = wn * 64 + ntp * 16 + (lane >> 4) * 8;
                        ldsm4t(bh, &Bs[buf][br * SBS + bc]);
                        b0 = bh[0]; b1 = bh[1]; c0 = bh[2]; c1 = bh[3];
                    }
                    #pragma unroll
                    for (int mt = 0; mt < 2; mt++) {
                        mma16816(acc[mt][2*ntp],   ah[mt], b0, b1);
                        mma16816(acc[mt][2*ntp+1], ah[mt], c0, c1);
                    }
                }
            }
            __syncthreads();
        }
    }

    // ---- epilogue ----
    const int er = lane >> 2, ec = 2 * (lane & 3);
    #pragma unroll
    for (int mt = 0; mt < 2; mt++) {
        #pragma unroll
        for (int nt = 0; nt < 8; nt++) {
            #pragma unroll
            for (int q2 = 0; q2 < 2; q2++) {
                const int m  = by * BM + wm * 32 + mt * 16 + er + q2 * 8;
                const int n0 = bx * BN + wn * 64 + nt * 8 + ec;
                const float v0 = acc[mt][nt][2*q2], v1 = acc[mt][nt][2*q2+1];
                if constexpr (MODE == 0) {
                    *(bf162*)&g_q[(size_t)m * DD + n0] = pack2(v0*0.125f, v1*0.125f);
                } else if constexpr (MODE == 1) {
                    const int head = n0 >> 7, rem = n0 & 127;
                    const int g2 = head >> 2, h = head & 3;
                    if (rem < 64)
                        *(bf162*)&g_kb[((size_t)g2*LL + m)*GDIM + h*64 + rem] = pack2(v0, v1);
                    else
                        *(bf162*)&g_vb[((size_t)g2*LL + m)*GDIM + h*64 + rem - 64] = pack2(v0, v1);
                } else if constexpr (MODE == 2) {
                    *(bf162*)&g_s[(size_t)bz*LL*LL + (size_t)m*LL + n0] = pack2(v0, v1);
                } else if constexpr (MODE == 3) {
                    *(bf162*)&g_ob[(size_t)m*DD + bz*GDIM + n0] = pack2(v0, v1);
                } else {
                    g_y[(size_t)m*DD + n0]     = v0 + P0[(size_t)m*DD + n0];
                    g_y[(size_t)m*DD + n0 + 1] = v1 + P0[(size_t)m*DD + n0 + 1];
                }
            }
        }
    }
}

// ---------------------------------------------------------------------------
// Row softmax over bf16 g_s, in place. One CTA per row; grid = 16*LL.
// ---------------------------------------------------------------------------
__global__ __launch_bounds__(256)
void softmax_k()
{
    bf16* S = g_s + (size_t)blockIdx.x * LL;
    const int tid = threadIdx.x;
    __shared__ float sh[8];
    uint4 raw = *(const uint4*)(S + tid * 8);
    const bf162* p2 = (const bf162*)&raw;
    float v[8];
    #pragma unroll
    for (int i = 0; i < 4; i++) {
        float2 f = __bfloat1622float2(p2[i]);
        v[2*i] = f.x; v[2*i+1] = f.y;
    }
    float m = -1e30f;
    #pragma unroll
    for (int i = 0; i < 8; i++) m = fmaxf(m, v[i]);
    #pragma unroll
    for (int o = 16; o > 0; o >>= 1) m = fmaxf(m, __shfl_xor_sync(0xffffffffu, m, o));
    if ((tid & 31) == 0) sh[tid >> 5] = m;
    __syncthreads();
    float tm = sh[0];
    #pragma unroll
    for (int w = 1; w < 8; w++) tm = fmaxf(tm, sh[w]);
    __syncthreads();
    float s = 0.f;
    #pragma unroll
    for (int i = 0; i < 8; i++) { v[i] = __expf(v[i] - tm); s += v[i]; }
    #pragma unroll
    for (int o = 16; o > 0; o >>= 1) s += __shfl_xor_sync(0xffffffffu, s, o);
    if ((tid & 31) == 0) sh[tid >> 5] = s;
    __syncthreads();
    float tot = 0.f;
    #pragma unroll
    for (int w = 0; w < 8; w++) tot += sh[w];
    const float inv = 1.0f / tot;
    uint4 out;
    bf162* o2 = (bf162*)&out;
    #pragma unroll
    for (int i = 0; i < 4; i++) o2[i] = pack2(v[2*i] * inv, v[2*i+1] * inv);
    *(uint4*)(S + tid * 8) = out;
}

// ---------------------------------------------------------------------------
// LayerNorm over g_y rows -> out. One CTA per row.
// ---------------------------------------------------------------------------
__global__ __launch_bounds__(256)
void ln_k(const float* __restrict__ gamma, const float* __restrict__ beta,
          float* __restrict__ out)
{
    const int row = blockIdx.x;
    const float* y = g_y + (size_t)row * DD;
    const int tid = threadIdx.x;
    __shared__ float sh[8];
    float v[4]; float s = 0.f;
    #pragma unroll
    for (int i = 0; i < 4; i++) { v[i] = y[tid + i * 256]; s += v[i]; }
    #pragma unroll
    for (int o = 16; o > 0; o >>= 1) s += __shfl_xor_sync(0xffffffffu, s, o);
    if ((tid & 31) == 0) sh[tid >> 5] = s;
    __syncthreads();
    float tot = 0.f;
    #pragma unroll
    for (int w = 0; w < 8; w++) tot += sh[w];
    const float mu = tot * (1.0f / 1024.0f);
    __syncthreads();
    float s2 = 0.f;
    #pragma unroll
    for (int i = 0; i < 4; i++) { const float d = v[i] - mu; s2 += d * d; }
    #pragma unroll
    for (int o = 16; o > 0; o >>= 1) s2 += __shfl_xor_sync(0xffffffffu, s2, o);
    if ((tid & 31) == 0) sh[tid >> 5] = s2;
    __syncthreads();
    float tot2 = 0.f;
    #pragma unroll
    for (int w = 0; w < 8; w++) tot2 += sh[w];
    const float r = rsqrtf(tot2 * (1.0f / 1024.0f) + 1e-5f);
    #pragma unroll
    for (int i = 0; i < 4; i++) {
        const int c = tid + i * 256;
        out[(size_t)row * DD + c] = gamma[c] * (v[i] - mu) * r + beta[c];
    }
}

extern "C" void kernel_launch(void* const* d_in, const int* in_sizes, int n_in,
                              void* d_out, int out_size)
{
    const float* x     = (const float*)d_in[0];
    const float* Wq    = (const float*)d_in[1];
    const float* Wkv   = (const float*)d_in[2];
    const float* Wo    = (const float*)d_in[3];
    const float* gamma = (const float*)d_in[4];
    const float* beta  = (const float*)d_in[5];
    float* out = (float*)d_out;
    (void)in_sizes; (void)n_in; (void)out_size;

    bf16 *xb, *wq, *wkv, *wo;
    cudaGetSymbolAddress((void**)&xb,  g_xb);
    cudaGetSymbolAddress((void**)&wq,  g_wq);
    cudaGetSymbolAddress((void**)&wkv, g_wkv);
    cudaGetSymbolAddress((void**)&wo,  g_wo);

    dim3 blk(256);
    cvt_k<<<LL*DD/1024,   blk>>>(x,   xb,  LL*DD);
    cvt_k<<<DD*DD/1024,   blk>>>(Wq,  wq,  DD*DD);
    cvt_k<<<2*DD*DD/1024, blk>>>(Wkv, wkv, 2*DD*DD);
    cvt_k<<<DD*DD/1024,   blk>>>(Wo,  wo,  DD*DD);

    gemm_tc<0><<<dim3( 8, 16    ), blk>>>(nullptr);  // Q proj (scaled)
    gemm_tc<1><<<dim3(16, 16    ), blk>>>(nullptr);  // KV proj + scatter
    gemm_tc<2><<<dim3(16, 16, 16), blk>>>(nullptr);  // 16 (g,G) score GEMMs
    softmax_k<<<16 * LL, blk>>>();                   // row softmax
    gemm_tc<3><<<dim3( 2, 16,  4), blk>>>(nullptr);  // O_g = sum_G P@V
    gemm_tc<4><<<dim3( 8, 16    ), blk>>>(x);        // Y = x + O@Wo^T
    ln_k<<<LL, blk>>>(gamma, beta, out);             // LayerNorm -> out
}

// round 6
// speedup vs baseline: 8.4593x; 1.1682x over previous
#include <cuda_runtime.h>
#include <cuda_bf16.h>
#include <cstdint>

#define LL 2048
#define DD 1024
#define GDIM 256

typedef __nv_bfloat16 bf16;
typedef __nv_bfloat162 bf162;

// Scratch (device globals; allocation in kernel_launch is forbidden)
__device__ bf16  g_xb [LL*DD];
__device__ bf16  g_wq [DD*DD];
__device__ bf16  g_wkv[2*DD*DD];
__device__ bf16  g_wo [DD*DD];
__device__ bf16  g_q  [LL*DD];        // Q bf16, pre-scaled by 1/8
__device__ bf16  g_kb [4*LL*GDIM];    // K per group [G][L][256]
__device__ bf16  g_vb [4*LL*GDIM];    // V per group [G][L][256]
__device__ bf16  g_s  [16u*LL*LL];    // scores/probs bf16, 16 slots (134 MB)
__device__ float g_of4[4u*LL*DD];     // per-G fp32 partials of O (32 MB)
__device__ bf16  g_ob [LL*DD];        // attention output bf16
__device__ float g_y  [LL*DD];        // pre-LN residual fp32

// ---------------------------------------------------------------------------
// PTX wrappers
// ---------------------------------------------------------------------------
__device__ __forceinline__ void ldsm4(uint32_t* r, const bf16* p) {
    uint32_t a = (uint32_t)__cvta_generic_to_shared(p);
    asm volatile("ldmatrix.sync.aligned.m8n8.x4.shared.b16 {%0,%1,%2,%3}, [%4];"
                 : "=r"(r[0]), "=r"(r[1]), "=r"(r[2]), "=r"(r[3]) : "r"(a));
}
__device__ __forceinline__ void ldsm4t(uint32_t* r, const bf16* p) {
    uint32_t a = (uint32_t)__cvta_generic_to_shared(p);
    asm volatile("ldmatrix.sync.aligned.m8n8.x4.trans.shared.b16 {%0,%1,%2,%3}, [%4];"
                 : "=r"(r[0]), "=r"(r[1]), "=r"(r[2]), "=r"(r[3]) : "r"(a));
}
__device__ __forceinline__ void mma16816(float* c, const uint32_t* a,
                                         uint32_t b0, uint32_t b1) {
    asm volatile("mma.sync.aligned.m16n8k16.row.col.f32.bf16.bf16.f32 "
                 "{%0,%1,%2,%3}, {%4,%5,%6,%7}, {%8,%9}, {%0,%1,%2,%3};"
                 : "+f"(c[0]), "+f"(c[1]), "+f"(c[2]), "+f"(c[3])
                 : "r"(a[0]), "r"(a[1]), "r"(a[2]), "r"(a[3]), "r"(b0), "r"(b1));
}
__device__ __forceinline__ void cp16(bf16* dst, const bf16* src) {
    uint32_t d = (uint32_t)__cvta_generic_to_shared(dst);
    asm volatile("cp.async.cg.shared.global [%0], [%1], 16;" :: "r"(d), "l"(src) : "memory");
}
__device__ __forceinline__ void cp_commit() {
    asm volatile("cp.async.commit_group;" ::: "memory");
}
template<int N>
__device__ __forceinline__ void cp_wait() {
    asm volatile("cp.async.wait_group %0;" :: "n"(N) : "memory");
}
__device__ __forceinline__ bf162 pack2(float a, float b) {
    bf162 r; r.x = __float2bfloat16_rn(a); r.y = __float2bfloat16_rn(b); return r;
}

// ---------------------------------------------------------------------------
// Fused input conversion: blockIdx.y selects segment (x, Wq, Wkv, Wo).
// ---------------------------------------------------------------------------
__global__ __launch_bounds__(256)
void cvt_all_k(const float* __restrict__ x,  const float* __restrict__ Wq,
               const float* __restrict__ Wkv, const float* __restrict__ Wo)
{
    const float* src; bf16* dst; int n;
    switch (blockIdx.y) {
        case 0: src = x;   dst = g_xb;  n = LL*DD;   break;
        case 1: src = Wq;  dst = g_wq;  n = DD*DD;   break;
        case 2: src = Wkv; dst = g_wkv; n = 2*DD*DD; break;
        default:src = Wo;  dst = g_wo;  n = DD*DD;   break;
    }
    const int i = (blockIdx.x * 256 + threadIdx.x) * 4;
    if (i < n) {
        float4 v = *(const float4*)(src + i);
        *(bf162*)(dst + i)     = pack2(v.x, v.y);
        *(bf162*)(dst + i + 2) = pack2(v.z, v.w);
    }
}

// Sum the 4 per-G fp32 partials -> bf16 O
__global__ __launch_bounds__(256)
void cvt_o_k()
{
    const int i = (blockIdx.x * 256 + threadIdx.x) * 4;
    float4 a = *(const float4*)(g_of4 + i);
    float4 b = *(const float4*)(g_of4 + (size_t)LL*DD + i);
    float4 c = *(const float4*)(g_of4 + 2u*(size_t)LL*DD + i);
    float4 d = *(const float4*)(g_of4 + 3u*(size_t)LL*DD + i);
    *(bf162*)(g_ob + i)     = pack2(a.x+b.x+c.x+d.x, a.y+b.y+c.y+d.y);
    *(bf162*)(g_ob + i + 2) = pack2(a.z+b.z+c.z+d.z, a.w+b.w+c.w+d.w);
}

// ---------------------------------------------------------------------------
// bf16 tensor-core GEMM, cp.async 3-stage pipeline, dynamic smem.
// 128x128x32 tiles, 8 warps (4m x 2n), warp tile 32x64, mma.sync m16n8k16.
// MODE 0: Q = x@Wq^T * 0.125       -> g_q
// MODE 1: KV = x@Wkv^T, scatter    -> g_kb/g_vb
// MODE 2: S = Q_g @ K_G^T ; bz = slot = g*4+G -> g_s
// MODE 3: partial O: P_slot @ V_G ; bz = slot; out -> g_of4[G] (fp32)
// MODE 4: Y = x + O@Wo^T           -> g_y
// ---------------------------------------------------------------------------
template<int MODE>
__global__ __launch_bounds__(256, 2)
void gemm_tc(const float* __restrict__ P0)
{
    constexpr int BM = 128, BN = 128, BK = 32;
    constexpr int SA  = 40;
    constexpr int SBR = (MODE == 3) ? BK : BN;
    constexpr int SBS = (MODE == 3) ? 136 : 40;
    constexpr int ASZ = BM * SA, BSZ = SBR * SBS;
    extern __shared__ bf16 dsm[];
    bf16* Asb = dsm;
    bf16* Bsb = dsm + 3 * ASZ;

    const int tid = threadIdx.x, lane = tid & 31, w = tid >> 5;
    const int wm = w & 3, wn = w >> 2;
    const int bx = blockIdx.x, by = blockIdx.y, bz = blockIdx.z;

    float acc[2][8][4];
    #pragma unroll
    for (int i = 0; i < 2; i++)
        #pragma unroll
        for (int j = 0; j < 8; j++)
            #pragma unroll
            for (int k = 0; k < 4; k++) acc[i][j][k] = 0.f;

    const bf16* Ab; const bf16* Bb; int lda, ldb, Ks;
    if constexpr (MODE == 0) {
        Ab = g_xb; Bb = g_wq;  lda = DD; ldb = DD; Ks = DD;
    } else if constexpr (MODE == 1) {
        Ab = g_xb; Bb = g_wkv; lda = DD; ldb = DD; Ks = DD;
    } else if constexpr (MODE == 2) {
        const int g = bz >> 2, G = bz & 3;
        Ab = g_q + g * GDIM;               lda = DD;   Ks = GDIM;
        Bb = g_kb + (size_t)G * LL * GDIM; ldb = GDIM;
    } else if constexpr (MODE == 3) {
        const int G = bz & 3;
        Ab = g_s + (size_t)bz * LL * LL;   lda = LL;   Ks = LL;
        Bb = g_vb + (size_t)G * LL * GDIM; ldb = GDIM;
    } else {
        Ab = g_ob; Bb = g_wo; lda = DD; ldb = DD; Ks = DD;
    }

    // stage loader (cp.async)
    auto stage = [&](int buf, int k0) {
        bf16* As = Asb + buf * ASZ;
        bf16* Bs = Bsb + buf * BSZ;
        {
            const int sr = tid >> 1, sc = (tid & 1) * 16;
            const bf16* ap = Ab + (size_t)(by * BM + sr) * lda + k0 + sc;
            cp16(&As[sr * SA + sc],     ap);
            cp16(&As[sr * SA + sc + 8], ap + 8);
        }
        if constexpr (MODE != 3) {
            const int sr = tid >> 1, sc = (tid & 1) * 16;
            const bf16* bp = Bb + (size_t)(bx * BN + sr) * ldb + k0 + sc;
            cp16(&Bs[sr * SBS + sc],     bp);
            cp16(&Bs[sr * SBS + sc + 8], bp + 8);
        } else {
            const int sr = tid >> 3, sc = (tid & 7) * 16;
            const bf16* bp = Bb + (size_t)(k0 + sr) * ldb + bx * BN + sc;
            cp16(&Bs[sr * SBS + sc],     bp);
            cp16(&Bs[sr * SBS + sc + 8], bp + 8);
        }
        cp_commit();
    };

    const int nk = Ks / BK;
    stage(0, 0);
    stage(1, BK);
    for (int ki = 0; ki < nk; ki++) {
        const int buf = ki % 3;
        if (ki == nk - 1) cp_wait<0>(); else cp_wait<1>();
        __syncthreads();
        if (ki + 2 < nk) stage((ki + 2) % 3, (ki + 2) * BK);

        const bf16* As = Asb + buf * ASZ;
        const bf16* Bs = Bsb + buf * BSZ;
        #pragma unroll
        for (int ks = 0; ks < 2; ks++) {
            uint32_t ah[2][4];
            const int ar = wm * 32 + (lane & 15);
            const int ac = ks * 16 + (lane >> 4) * 8;
            #pragma unroll
            for (int mt = 0; mt < 2; mt++)
                ldsm4(ah[mt], &As[(ar + mt * 16) * SA + ac]);
            #pragma unroll
            for (int ntp = 0; ntp < 4; ntp++) {
                uint32_t bh[4];
                uint32_t b0, b1, c0, c1;
                if constexpr (MODE != 3) {
                    const int br = wn * 64 + ntp * 16 + (lane & 15);
                    const int bc = ks * 16 + (lane >> 4) * 8;
                    ldsm4(bh, &Bs[br * SBS + bc]);
                    b0 = bh[0]; b1 = bh[2]; c0 = bh[1]; c1 = bh[3];
                } else {
                    const int br = ks * 16 + (lane & 15);
                    const int bc = wn * 64 + ntp * 16 + (lane >> 4) * 8;
                    ldsm4t(bh, &Bs[br * SBS + bc]);
                    b0 = bh[0]; b1 = bh[1]; c0 = bh[2]; c1 = bh[3];
                }
                #pragma unroll
                for (int mt = 0; mt < 2; mt++) {
                    mma16816(acc[mt][2*ntp],   ah[mt], b0, b1);
                    mma16816(acc[mt][2*ntp+1], ah[mt], c0, c1);
                }
            }
        }
        __syncthreads();
    }

    // ---- epilogue ----
    const int er = lane >> 2, ec = 2 * (lane & 3);
    #pragma unroll
    for (int mt = 0; mt < 2; mt++) {
        #pragma unroll
        for (int nt = 0; nt < 8; nt++) {
            #pragma unroll
            for (int q2 = 0; q2 < 2; q2++) {
                const int m  = by * BM + wm * 32 + mt * 16 + er + q2 * 8;
                const int n0 = bx * BN + wn * 64 + nt * 8 + ec;
                const float v0 = acc[mt][nt][2*q2], v1 = acc[mt][nt][2*q2+1];
                if constexpr (MODE == 0) {
                    *(bf162*)&g_q[(size_t)m * DD + n0] = pack2(v0*0.125f, v1*0.125f);
                } else if constexpr (MODE == 1) {
                    const int head = n0 >> 7, rem = n0 & 127;
                    const int g2 = head >> 2, h = head & 3;
                    if (rem < 64)
                        *(bf162*)&g_kb[((size_t)g2*LL + m)*GDIM + h*64 + rem] = pack2(v0, v1);
                    else
                        *(bf162*)&g_vb[((size_t)g2*LL + m)*GDIM + h*64 + rem - 64] = pack2(v0, v1);
                } else if constexpr (MODE == 2) {
                    *(bf162*)&g_s[(size_t)bz*LL*LL + (size_t)m*LL + n0] = pack2(v0, v1);
                } else if constexpr (MODE == 3) {
                    const int g = bz >> 2, G = bz & 3;
                    float* dst = g_of4 + (size_t)G*LL*DD + (size_t)m*DD + g*GDIM + n0;
                    dst[0] = v0; dst[1] = v1;
                } else {
                    g_y[(size_t)m*DD + n0]     = v0 + P0[(size_t)m*DD + n0];
                    g_y[(size_t)m*DD + n0 + 1] = v1 + P0[(size_t)m*DD + n0 + 1];
                }
            }
        }
    }
}

// ---------------------------------------------------------------------------
// Row softmax over bf16 g_s, in place. One CTA per row; grid = 16*LL.
// ---------------------------------------------------------------------------
__global__ __launch_bounds__(256)
void softmax_k()
{
    bf16* S = g_s + (size_t)blockIdx.x * LL;
    const int tid = threadIdx.x;
    __shared__ float sh[8];
    uint4 raw = *(const uint4*)(S + tid * 8);
    const bf162* p2 = (const bf162*)&raw;
    float v[8];
    #pragma unroll
    for (int i = 0; i < 4; i++) {
        float2 f = __bfloat1622float2(p2[i]);
        v[2*i] = f.x; v[2*i+1] = f.y;
    }
    float m = -1e30f;
    #pragma unroll
    for (int i = 0; i < 8; i++) m = fmaxf(m, v[i]);
    #pragma unroll
    for (int o = 16; o > 0; o >>= 1) m = fmaxf(m, __shfl_xor_sync(0xffffffffu, m, o));
    if ((tid & 31) == 0) sh[tid >> 5] = m;
    __syncthreads();
    float tm = sh[0];
    #pragma unroll
    for (int w = 1; w < 8; w++) tm = fmaxf(tm, sh[w]);
    __syncthreads();
    float s = 0.f;
    #pragma unroll
    for (int i = 0; i < 8; i++) { v[i] = __expf(v[i] - tm); s += v[i]; }
    #pragma unroll
    for (int o = 16; o > 0; o >>= 1) s += __shfl_xor_sync(0xffffffffu, s, o);
    if ((tid & 31) == 0) sh[tid >> 5] = s;
    __syncthreads();
    float tot = 0.f;
    #pragma unroll
    for (int w = 0; w < 8; w++) tot += sh[w];
    const float inv = 1.0f / tot;
    uint4 out;
    bf162* o2 = (bf162*)&out;
    #pragma unroll
    for (int i = 0; i < 4; i++) o2[i] = pack2(v[2*i] * inv, v[2*i+1] * inv);
    *(uint4*)(S + tid * 8) = out;
}

// ---------------------------------------------------------------------------
// LayerNorm over g_y rows -> out. One CTA per row.
// ---------------------------------------------------------------------------
__global__ __launch_bounds__(256)
void ln_k(const float* __restrict__ gamma, const float* __restrict__ beta,
          float* __restrict__ out)
{
    const int row = blockIdx.x;
    const float* y = g_y + (size_t)row * DD;
    const int tid = threadIdx.x;
    __shared__ float sh[8];
    float v[4]; float s = 0.f;
    #pragma unroll
    for (int i = 0; i < 4; i++) { v[i] = y[tid + i * 256]; s += v[i]; }
    #pragma unroll
    for (int o = 16; o > 0; o >>= 1) s += __shfl_xor_sync(0xffffffffu, s, o);
    if ((tid & 31) == 0) sh[tid >> 5] = s;
    __syncthreads();
    float tot = 0.f;
    #pragma unroll
    for (int w = 0; w < 8; w++) tot += sh[w];
    const float mu = tot * (1.0f / 1024.0f);
    __syncthreads();
    float s2 = 0.f;
    #pragma unroll
    for (int i = 0; i < 4; i++) { const float d = v[i] - mu; s2 += d * d; }
    #pragma unroll
    for (int o = 16; o > 0; o >>= 1) s2 += __shfl_xor_sync(0xffffffffu, s2, o);
    if ((tid & 31) == 0) sh[tid >> 5] = s2;
    __syncthreads();
    float tot2 = 0.f;
    #pragma unroll
    for (int w = 0; w < 8; w++) tot2 += sh[w];
    const float r = rsqrtf(tot2 * (1.0f / 1024.0f) + 1e-5f);
    #pragma unroll
    for (int i = 0; i < 4; i++) {
        const int c = tid + i * 256;
        out[(size_t)row * DD + c] = gamma[c] * (v[i] - mu) * r + beta[c];
    }
}

extern "C" void kernel_launch(void* const* d_in, const int* in_sizes, int n_in,
                              void* d_out, int out_size)
{
    const float* x     = (const float*)d_in[0];
    const float* Wq    = (const float*)d_in[1];
    const float* Wkv   = (const float*)d_in[2];
    const float* Wo    = (const float*)d_in[3];
    const float* gamma = (const float*)d_in[4];
    const float* beta  = (const float*)d_in[5];
    float* out = (float*)d_out;
    (void)in_sizes; (void)n_in; (void)out_size;

    // dynamic smem sizes (3-stage)
    const int smemAB = 3 * (128*40 + 128*40) * 2;   // modes 0,1,2,4: 61440 B
    const int smemM3 = 3 * (128*40 + 32*136) * 2;   // mode 3:        56832 B
    static bool attr_done = false;
    if (!attr_done) {
        cudaFuncSetAttribute(gemm_tc<0>, cudaFuncAttributeMaxDynamicSharedMemorySize, smemAB);
        cudaFuncSetAttribute(gemm_tc<1>, cudaFuncAttributeMaxDynamicSharedMemorySize, smemAB);
        cudaFuncSetAttribute(gemm_tc<2>, cudaFuncAttributeMaxDynamicSharedMemorySize, smemAB);
        cudaFuncSetAttribute(gemm_tc<3>, cudaFuncAttributeMaxDynamicSharedMemorySize, smemM3);
        cudaFuncSetAttribute(gemm_tc<4>, cudaFuncAttributeMaxDynamicSharedMemorySize, smemAB);
        attr_done = true;
    }

    dim3 blk(256);
    cvt_all_k<<<dim3(2048, 4), blk>>>(x, Wq, Wkv, Wo);        // all input cvts

    gemm_tc<0><<<dim3( 8, 16    ), blk, smemAB>>>(nullptr);   // Q proj (scaled)
    gemm_tc<1><<<dim3(16, 16    ), blk, smemAB>>>(nullptr);   // KV proj + scatter
    gemm_tc<2><<<dim3(16, 16, 16), blk, smemAB>>>(nullptr);   // 16 (g,G) score GEMMs
    softmax_k<<<16 * LL, blk>>>();                            // row softmax
    gemm_tc<3><<<dim3( 2, 16, 16), blk, smemM3>>>(nullptr);   // per-G partial O (fp32)
    cvt_o_k<<<LL*DD/1024, blk>>>();                           // sum partials -> bf16 O
    gemm_tc<4><<<dim3( 8, 16    ), blk, smemAB>>>(x);         // Y = x + O@Wo^T
    ln_k<<<LL, blk>>>(gamma, beta, out);                      // LayerNorm -> out
}